// round 2
// baseline (speedup 1.0000x reference)
#include <cuda_runtime.h>

#define TPB 128

__global__ void __launch_bounds__(TPB, 1)
tps_kernel(const float* __restrict__ u,
           const float* __restrict__ cp,
           const float* __restrict__ w,
           const float* __restrict__ poly,
           float* __restrict__ out,
           int batch, int n) {
    extern __shared__ float4 smem[];
    float4* s_c = smem;       // {-2cx, -2cy, -2cz, |c|^2}
    float4* s_w = smem + n;   // {w0, w1, w2, 0}

    // Stage + transform control points and weights into shared memory.
    for (int j = threadIdx.x; j < n; j += TPB) {
        float cx = cp[3 * j + 0];
        float cy = cp[3 * j + 1];
        float cz = cp[3 * j + 2];
        float c2 = fmaf(cx, cx, fmaf(cy, cy, cz * cz));
        s_c[j] = make_float4(-2.0f * cx, -2.0f * cy, -2.0f * cz, c2);
        s_w[j] = make_float4(w[3 * j + 0], w[3 * j + 1], w[3 * j + 2], 0.0f);
    }
    __syncthreads();

    int row = blockIdx.x * TPB + threadIdx.x;
    if (row >= batch) return;

    float ux = u[3 * row + 0];
    float uy = u[3 * row + 1];
    float uz = u[3 * row + 2];
    float u2 = fmaf(ux, ux, fmaf(uy, uy, uz * uz));

    float a0 = 0.0f, a1 = 0.0f, a2 = 0.0f;

    #pragma unroll 8
    for (int j = 0; j < n; ++j) {
        float4 c  = s_c[j];
        float4 wj = s_w[j];
        // sq = |u|^2 + |c|^2 - 2 u.c   (expanded form, matches reference cdist)
        float sq = fmaf(c.x, ux, fmaf(c.y, uy, fmaf(c.z, uz, u2 + c.w)));
        // clamp >= 0 and absorb the r<EPS -> 0 branch: sq=1e-20 gives k ~ -6.6e-9
        sq = fmaxf(sq, 1e-20f);
        float r, lg;
        asm("sqrt.approx.f32 %0, %1;" : "=f"(r)  : "f"(sq));
        asm("lg2.approx.f32 %0, %1;"  : "=f"(lg) : "f"(sq));
        // k_unscaled = sqrt(sq) * lg2(sq);  true k = 0.5*ln2 * k_unscaled
        float k = r * lg;
        a0 = fmaf(k, wj.x, a0);
        a1 = fmaf(k, wj.y, a1);
        a2 = fmaf(k, wj.z, a2);
    }

    const float C = 0.34657359027997264f;  // 0.5 * ln(2)
    // poly: (4, 3) row-major; P = [1, ux, uy, uz]
    float p0 = poly[0] + fmaf(ux, poly[3], fmaf(uy, poly[6], uz * poly[9]));
    float p1 = poly[1] + fmaf(ux, poly[4], fmaf(uy, poly[7], uz * poly[10]));
    float p2 = poly[2] + fmaf(ux, poly[5], fmaf(uy, poly[8], uz * poly[11]));

    out[3 * row + 0] = fmaf(C, a0, p0);
    out[3 * row + 1] = fmaf(C, a1, p1);
    out[3 * row + 2] = fmaf(C, a2, p2);
}

extern "C" void kernel_launch(void* const* d_in, const int* in_sizes, int n_in,
                              void* d_out, int out_size) {
    const float* u    = (const float*)d_in[0];
    const float* cp   = (const float*)d_in[1];
    const float* w    = (const float*)d_in[2];
    const float* poly = (const float*)d_in[3];
    float* out = (float*)d_out;

    int batch = in_sizes[0] / 3;
    int n     = in_sizes[1] / 3;

    size_t smem_bytes = (size_t)2 * n * sizeof(float4);
    cudaFuncSetAttribute(tps_kernel,
                         cudaFuncAttributeMaxDynamicSharedMemorySize,
                         (int)smem_bytes);

    int blocks = (batch + TPB - 1) / TPB;
    tps_kernel<<<blocks, TPB, smem_bytes>>>(u, cp, w, poly, out, batch, n);
}

// round 4
// speedup vs baseline: 1.4750x; 1.4750x over previous
#include <cuda_runtime.h>

#define TPB 512
#define ROWS_PER_CTA 128
#define JSPLIT 4

__global__ void __launch_bounds__(TPB, 1)
tps_kernel(const float* __restrict__ u,
           const float* __restrict__ cp,
           const float* __restrict__ w,
           const float* __restrict__ poly,
           float* __restrict__ out,
           int batch, int n) {
    extern __shared__ float smem_raw[];
    float4* s_c   = (float4*)smem_raw;                 // n   {-2cx,-2cy,-2cz,|c|^2}
    float4* s_w   = s_c + n;                           // n   {w0,w1,w2,0}
    float*  s_red = (float*)(s_w + n);                 // (JSPLIT-1)*ROWS_PER_CTA*3

    // Stage + transform control points and weights into shared memory.
    for (int j = threadIdx.x; j < n; j += TPB) {
        float cx = cp[3 * j + 0];
        float cy = cp[3 * j + 1];
        float cz = cp[3 * j + 2];
        float c2 = fmaf(cx, cx, fmaf(cy, cy, cz * cz));
        s_c[j] = make_float4(-2.0f * cx, -2.0f * cy, -2.0f * cz, c2);
        s_w[j] = make_float4(w[3 * j + 0], w[3 * j + 1], w[3 * j + 2], 0.0f);
    }
    __syncthreads();

    // Thread layout: 128 rows x 4 j-chunks. Warps stay within one chunk.
    int row_local = threadIdx.x & (ROWS_PER_CTA - 1);
    int chunk     = threadIdx.x >> 7;                   // 0..3
    int row       = blockIdx.x * ROWS_PER_CTA + row_local;
    int row_ok    = row < batch;
    int row_c     = row_ok ? row : 0;

    float ux = u[3 * row_c + 0];
    float uy = u[3 * row_c + 1];
    float uz = u[3 * row_c + 2];
    float u2 = fmaf(ux, ux, fmaf(uy, uy, uz * uz));

    float a0 = 0.0f, a1 = 0.0f, a2 = 0.0f;

    int jlen = n / JSPLIT;
    int j0 = chunk * jlen;
    int j1 = j0 + jlen;

    #pragma unroll 8
    for (int j = j0; j < j1; ++j) {
        float4 c  = s_c[j];
        float4 wj = s_w[j];
        // sq = |u|^2 + |c|^2 - 2 u.c   (expanded form, matches reference cdist)
        float sq = fmaf(c.x, ux, fmaf(c.y, uy, fmaf(c.z, uz, u2 + c.w)));
        sq = fmaxf(sq, 1e-20f);   // absorbs the r<EPS -> 0 branch (k ~ -6.6e-9)
        float r, lg;
        asm("sqrt.approx.f32 %0, %1;" : "=f"(r)  : "f"(sq));
        asm("lg2.approx.f32 %0, %1;"  : "=f"(lg) : "f"(sq));
        float k = r * lg;          // true k = 0.5*ln2 * (r * lg2(sq))
        a0 = fmaf(k, wj.x, a0);
        a1 = fmaf(k, wj.y, a1);
        a2 = fmaf(k, wj.z, a2);
    }

    // Reduce the 4 j-chunk partials per row.
    if (chunk > 0) {
        int base = ((chunk - 1) * ROWS_PER_CTA + row_local) * 3;
        s_red[base + 0] = a0;
        s_red[base + 1] = a1;
        s_red[base + 2] = a2;
    }
    __syncthreads();

    if (chunk == 0 && row_ok) {
        #pragma unroll
        for (int c = 0; c < JSPLIT - 1; ++c) {
            int base = (c * ROWS_PER_CTA + row_local) * 3;
            a0 += s_red[base + 0];
            a1 += s_red[base + 1];
            a2 += s_red[base + 2];
        }
        const float C = 0.34657359027997264f;   // 0.5 * ln(2)
        // poly: (4, 3) row-major; P = [1, ux, uy, uz]
        float p0 = poly[0] + fmaf(ux, poly[3], fmaf(uy, poly[6], uz * poly[9]));
        float p1 = poly[1] + fmaf(ux, poly[4], fmaf(uy, poly[7], uz * poly[10]));
        float p2 = poly[2] + fmaf(ux, poly[5], fmaf(uy, poly[8], uz * poly[11]));
        out[3 * row + 0] = fmaf(C, a0, p0);
        out[3 * row + 1] = fmaf(C, a1, p1);
        out[3 * row + 2] = fmaf(C, a2, p2);
    }
}

extern "C" void kernel_launch(void* const* d_in, const int* in_sizes, int n_in,
                              void* d_out, int out_size) {
    const float* u    = (const float*)d_in[0];
    const float* cp   = (const float*)d_in[1];
    const float* w    = (const float*)d_in[2];
    const float* poly = (const float*)d_in[3];
    float* out = (float*)d_out;

    int batch = in_sizes[0] / 3;
    int n     = in_sizes[1] / 3;

    size_t smem_bytes = (size_t)2 * n * sizeof(float4)
                      + (size_t)(JSPLIT - 1) * ROWS_PER_CTA * 3 * sizeof(float);
    cudaFuncSetAttribute(tps_kernel,
                         cudaFuncAttributeMaxDynamicSharedMemorySize,
                         (int)smem_bytes);

    int blocks = (batch + ROWS_PER_CTA - 1) / ROWS_PER_CTA;
    tps_kernel<<<blocks, TPB, smem_bytes>>>(u, cp, w, poly, out, batch, n);
}